// round 11
// baseline (speedup 1.0000x reference)
#include <cuda_runtime.h>
#include <cuda_bf16.h>
#include <cuda_fp16.h>

// emb[b,f,e] = b2[f,e] + sum_h W2[f,e,h]*relu(x[b,f]*W1[f,h]+b1[f,h])
// Piecewise-linear-in-x: per f, 65 segments; emb = A(seg)*x + C(seg).
// fp16 segment row (64B): 8 x {half2 A, half2 C}.
// Segment lookup: 512-bucket LUT (uchar2 bounds) + rare exact refinement.

#define BN 16384
#define FN 128
#define HN 64
#define EN 16
#define THR_S 72        // threshold stride (bank spread across ff)
#define TAB_S 524       // smem table stride in h4 units
#define NB   512        // buckets
#define LUT_S 520       // smem lut stride

#define BUCK_LO (-6.0f)
#define BUCK_SC ((float)NB / 12.0f)

struct __align__(8) h4 { __half2 a, c; };

__device__ h4     g_tab_h[FN * 520];     // per f: 65 segs * 8 h4
__device__ float  g_thr[FN * 64];        // sorted hinge thresholds per f
__device__ uchar2 g_lutp[FN * (NB + 1)]; // (lut[k], lut[k+1])

__device__ __forceinline__ int bucket_of(float v) {
    float p = (v - BUCK_LO) * BUCK_SC;
    p = fminf(fmaxf(p, 0.0f), (float)(NB - 1));
    return (int)p;
}

// ---------------------------------------------------------------------------
// Kernel 1: per-feature precompute. One block per f, 128 threads. (unchanged)
// ---------------------------------------------------------------------------
__global__ void __launch_bounds__(128) dfe_precompute(
    const float* __restrict__ W1, const float* __restrict__ b1,
    const float* __restrict__ W2, const float* __restrict__ b2)
{
    int f = blockIdx.x;
    int tid = threadIdx.x;

    __shared__ float sw[HN], sb[HN], tv_[HN], st[HN];
    __shared__ int   sidx[HN];
    __shared__ float sv[EN * HN];
    __shared__ float stab[65 * 32];
    __shared__ unsigned char slutc[NB + 1];

    for (int i = tid; i < EN * HN; i += 128) sv[i] = W2[f * EN * HN + i];

    if (tid < HN) {
        float w = W1[f * HN + tid];
        float b = b1[f * HN + tid];
        sw[tid] = w; sb[tid] = b;
        tv_[tid] = (w != 0.0f) ? (-b / w) : 3.0e38f;  // sentinel: never crossed
    }
    __syncthreads();

    // stable rank-sort of 64 thresholds
    if (tid < HN) {
        float tv = tv_[tid];
        int r = 0;
        for (int j = 0; j < HN; j++) {
            float tj = tv_[j];
            r += (tj < tv) || (tj == tv && j < tid);
        }
        st[r] = tv;
        sidx[r] = tid;
    }
    __syncthreads();

    if (tid < HN) g_thr[f * HN + tid] = st[tid];

    // LUT scatter: lut[k] = #{thr : bucket(thr) < k} is a step function of k.
    if (tid <= HN) {
        int blo = (tid == 0)  ? -1 : bucket_of(st[tid - 1]);
        int bhi = (tid == HN) ? NB : bucket_of(st[tid]);
        for (int k = blo + 1; k <= bhi && k <= NB; k++)
            slutc[k] = (unsigned char)tid;
    }

    // segment walk: 16 threads, one per e (all operands in smem)
    if (tid < EN) {
        int e = tid;
        const float* w2 = sv + e * HN;
        float A = 0.0f;
        float C = b2[f * EN + e];
        for (int h = 0; h < HN; h++) {
            float w = sw[h], b = sb[h], v = w2[h];
            float m = (w < 0.0f) ? 1.0f : 0.0f;            // active at x=-inf
            A += m * w * v;
            C += m * b * v;
            C += (w == 0.0f) ? fmaxf(b, 0.0f) * v : 0.0f;  // constant hinge
        }
        int grp = e >> 1, par = e & 1;
        for (int s = 0; s <= 64; s++) {
            stab[s * 32 + grp * 4 + par]     = A;
            stab[s * 32 + grp * 4 + 2 + par] = C;
            if (s < 64) {
                int h = sidx[s];
                float w = sw[h], b = sb[h], v = w2[h];
                float sg = (w > 0.0f) ? 1.0f : ((w < 0.0f) ? -1.0f : 0.0f);
                A += sg * w * v;
                C += sg * b * v;
            }
        }
    }
    __syncthreads();

    // LUT pair writeback
    for (int k = tid; k <= NB; k += 128) {
        unsigned char c0 = slutc[k];
        unsigned char c1 = (k < NB) ? slutc[k + 1] : c0;
        g_lutp[f * (NB + 1) + k] = make_uchar2(c0, c1);
    }

    // pack fp32 staging -> fp16 table, coalesced writeback
    for (int i = tid; i < 520; i += 128) {
        int s = i >> 3, j = i & 7;
        const float* p = stab + s * 32 + j * 4;
        h4 v;
        v.a = __floats2half2_rn(p[0], p[1]);
        v.c = __floats2half2_rn(p[2], p[3]);
        g_tab_h[f * 520 + i] = v;
    }
}

// ---------------------------------------------------------------------------
// Kernel 2: evaluation. Block = 4 features ("quad") x 512 rows, 256 threads.
// The block's x tile (512 rows x 4 feats = 8KB) is staged to smem up front
// with bulk float4 LDGs -> ZERO global loads in the main loop.
// Warp owns 64 rows as 8 batches of 8.
//   Phase 1: lane=(ff=lane>>3, rrow=lane&7): x from smem (1 conflict-free wf),
//     bucket-LUT lookup + rare refinement; (xs,seg) into double-buffered
//     exchange; one syncwarp per batch.
//   Phase 2: lane=(r01=lane>>4, ff2=(lane>>2)&3, j4=lane&3): 4 passes x 2 rows;
//     broadcast LDS.64 exchange read, LDS.128 table chunk, 4 FMA, STG.128
//     (512B contiguous per pass).
// ---------------------------------------------------------------------------
__global__ void __launch_bounds__(256, 6) dfe_eval(
    const float* __restrict__ x, float* __restrict__ out)
{
    __shared__ h4     stab[4 * TAB_S];
    __shared__ float  sthr[4 * THR_S];
    __shared__ uchar2 slut[4 * LUT_S];
    __shared__ float  sx[512 * 4];        // x tile: [row][ff]
    __shared__ float2 sxch[8][2][32];     // per-warp double-buffered exchange

    int tid = threadIdx.x;
    int quad = blockIdx.x;
    int bbase = blockIdx.y * 512;

    // ---- stage x tile (bulk, huge MLP) + tables ----
    {
        const float* xq = x + (size_t)bbase * FN + quad * 4;
        float4* sx4 = (float4*)sx;
        #pragma unroll
        for (int r = 0; r < 2; r++) {
            int row = r * 256 + tid;
            sx4[row] = *(const float4*)(xq + (size_t)row * FN);
        }
    }
    #pragma unroll
    for (int ff = 0; ff < 4; ff++)
        for (int i = tid; i < 520; i += 256)
            stab[ff * TAB_S + i] = g_tab_h[(quad * 4 + ff) * 520 + i];
    for (int i = tid; i < 4 * 64; i += 256)
        sthr[(i >> 6) * THR_S + (i & 63)] = g_thr[quad * 256 + i];
    for (int i = tid; i < 4 * (NB + 1); i += 256) {
        int ff = i / (NB + 1), k = i % (NB + 1);
        slut[ff * LUT_S + k] = g_lutp[(quad * 4 + ff) * (NB + 1) + k];
    }
    __syncthreads();

    int lane = tid & 31, w = tid >> 5;
    int rrow = lane & 7;            // phase-1 row within batch
    int ff   = lane >> 3;           // phase-1 feature
    int r01  = lane >> 4;           // phase-2 row parity
    int ff2  = (lane >> 2) & 3;     // phase-2 feature
    int j4   = lane & 3;            // phase-2 e-quad

    const float*  thrp = sthr + ff * THR_S;
    const uchar2* lutf = slut + ff * LUT_S;

    int rb0 = bbase + w * 64;
    const float* sxw  = sx + (w * 64) * 4;    // this warp's x rows
    float*       outb = out + (size_t)rb0 * (FN * EN) + quad * 64 + ff2 * 16 + j4 * 4;

    auto seg_search = [&](float xs) -> int {
        int k = bucket_of(xs);
        uchar2 pr = lutf[k];
        int seg = pr.x;
        for (int t = pr.x; t < pr.y; t++) seg += (thrp[t] <= xs);
        return seg;   // exact count in [0,64]
    };

    #pragma unroll
    for (int batch = 0; batch < 8; batch++) {
        // phase 1: all operands in smem; 1 conflict-free LDS for x
        float xs = sxw[(batch * 8 + rrow) * 4 + ff];
        int   seg = seg_search(xs);

        float2* xch = sxch[w][batch & 1];
        xch[lane] = make_float2(xs, __int_as_float(seg));
        __syncwarp();

        float* orow = outb + (size_t)(batch * 8) * (FN * EN);
        #pragma unroll
        for (int k = 0; k < 4; k++) {
            int row = k * 2 + r01;
            float2 e = xch[ff2 * 8 + row];           // broadcast across 4 j4 lanes
            int sg = __float_as_int(e.y);
            const h4* tp = stab + ff2 * TAB_S + sg * 8 + j4 * 2;   // 16B aligned
            uint4 raw = *(const uint4*)tp;
            h4 v0 = *(const h4*)&raw.x;
            h4 v1 = *(const h4*)&raw.z;
            float2 a0 = __half22float2(v0.a), c0 = __half22float2(v0.c);
            float2 a1 = __half22float2(v1.a), c1 = __half22float2(v1.c);
            float4 o;
            o.x = fmaf(a0.x, e.x, c0.x);
            o.y = fmaf(a0.y, e.x, c0.y);
            o.z = fmaf(a1.x, e.x, c1.x);
            o.w = fmaf(a1.y, e.x, c1.y);
            __stcs((float4*)(orow + (size_t)row * (FN * EN)), o);
        }
        // no trailing syncwarp: next batch writes the other exchange buffer;
        // this one is rewritten 2 batches later, past the next syncwarp.
    }
}

extern "C" void kernel_launch(void* const* d_in, const int* in_sizes, int n_in,
                              void* d_out, int out_size)
{
    const float* x  = (const float*)d_in[0];
    const float* W1 = (const float*)d_in[1];
    const float* b1 = (const float*)d_in[2];
    const float* W2 = (const float*)d_in[3];
    const float* b2 = (const float*)d_in[4];
    float* out = (float*)d_out;

    dfe_precompute<<<FN, 128>>>(W1, b1, W2, b2);
    dfe_eval<<<dim3(FN / 4, BN / 512), 256>>>(x, out);
}

// round 12
// speedup vs baseline: 1.1462x; 1.1462x over previous
#include <cuda_runtime.h>
#include <cuda_bf16.h>
#include <cuda_fp16.h>

// emb[b,f,e] = b2[f,e] + sum_h W2[f,e,h]*relu(x[b,f]*W1[f,h]+b1[f,h])
// Piecewise-linear-in-x: per f, 65 segments; emb = A(seg)*x + C(seg).
// fp16 segment row (64B): 8 x {half2 A, half2 C}.
// R12 = R5 inner loop, 4x rows/block (table refill amortized), 1 syncwarp/batch.

#define BN 16384
#define FN 128
#define HN 64
#define EN 16
#define THR_S 72        // threshold stride (bank spread across ff)
#define TAB_S 524       // smem table stride in h4 units
#define ROWS_PER_BLOCK 1024
#define BATCHES 16      // per warp: 128 rows = 16 batches of 8

struct __align__(8) h4 { __half2 a, c; };

__device__ h4    g_tab_h[FN * 520];   // per f: 65 segs * 8 h4
__device__ float g_thr[FN * 64];      // sorted hinge thresholds per f

// ---------------------------------------------------------------------------
// Kernel 1: per-feature precompute. One block per f, 128 threads. (R5 exact)
// ---------------------------------------------------------------------------
__global__ void __launch_bounds__(128) dfe_precompute(
    const float* __restrict__ W1, const float* __restrict__ b1,
    const float* __restrict__ W2, const float* __restrict__ b2)
{
    int f = blockIdx.x;
    int tid = threadIdx.x;

    __shared__ float sw[HN], sb[HN], tv_[HN], st[HN];
    __shared__ int   sidx[HN];
    __shared__ float sv[EN * HN];      // W2 row staged (kills serial LDGs in walk)
    __shared__ float stab[65 * 32];

    for (int i = tid; i < EN * HN; i += 128) sv[i] = W2[f * EN * HN + i];

    if (tid < HN) {
        float w = W1[f * HN + tid];
        float b = b1[f * HN + tid];
        sw[tid] = w; sb[tid] = b;
        tv_[tid] = (w != 0.0f) ? (-b / w) : 3.0e38f;  // sentinel: never crossed
    }
    __syncthreads();

    // stable rank-sort of 64 thresholds
    if (tid < HN) {
        float tv = tv_[tid];
        int r = 0;
        for (int j = 0; j < HN; j++) {
            float tj = tv_[j];
            r += (tj < tv) || (tj == tv && j < tid);
        }
        st[r] = tv;
        sidx[r] = tid;
    }
    __syncthreads();

    if (tid < HN) g_thr[f * HN + tid] = st[tid];

    // segment walk: 16 threads, one per e (all operands in smem)
    if (tid < EN) {
        int e = tid;
        const float* w2 = sv + e * HN;
        float A = 0.0f;
        float C = b2[f * EN + e];
        for (int h = 0; h < HN; h++) {
            float w = sw[h], b = sb[h], v = w2[h];
            float m = (w < 0.0f) ? 1.0f : 0.0f;            // active at x=-inf
            A += m * w * v;
            C += m * b * v;
            C += (w == 0.0f) ? fmaxf(b, 0.0f) * v : 0.0f;  // constant hinge
        }
        int grp = e >> 1, par = e & 1;
        for (int s = 0; s <= 64; s++) {
            stab[s * 32 + grp * 4 + par]     = A;
            stab[s * 32 + grp * 4 + 2 + par] = C;
            if (s < 64) {
                int h = sidx[s];
                float w = sw[h], b = sb[h], v = w2[h];
                float sg = (w > 0.0f) ? 1.0f : ((w < 0.0f) ? -1.0f : 0.0f);
                A += sg * w * v;
                C += sg * b * v;
            }
        }
    }
    __syncthreads();

    // pack fp32 staging -> fp16 table, coalesced writeback
    for (int i = tid; i < 520; i += 128) {
        int s = i >> 3, j = i & 7;
        const float* p = stab + s * 32 + j * 4;
        h4 v;
        v.a = __floats2half2_rn(p[0], p[1]);
        v.c = __floats2half2_rn(p[2], p[3]);
        g_tab_h[f * 520 + i] = v;
    }
}

// ---------------------------------------------------------------------------
// Branch-free count of { thr[t] <= xs } over 64 sorted entries (7 LDS). (R5)
// ---------------------------------------------------------------------------
__device__ __forceinline__ int seg_search(const float* __restrict__ thrp, float xs)
{
    int p = (thrp[31] <= xs) ? 32 : 0;
    p += (thrp[p + 15] <= xs) ? 16 : 0;
    p += (thrp[p + 7]  <= xs) ? 8  : 0;
    p += (thrp[p + 3]  <= xs) ? 4  : 0;
    p += (thrp[p + 1]  <= xs) ? 2  : 0;
    p += (thrp[p]      <= xs) ? 1  : 0;
    return p + ((thrp[p] <= xs) ? 1 : 0);   // in [0,64]
}

// ---------------------------------------------------------------------------
// Kernel 2: evaluation. Block = 4 features ("quad") x 1024 rows, 256 threads.
// Warp owns 128 rows as 16 batches of 8. (R5 inner loop; tables loaded once
// per 1024 rows instead of per 512 -> table refill traffic 76MB -> 19MB.)
// Phase 1: lane=(ff=lane>>3, rrow=lane&7): 32 distinct searches; results via
//   double-buffered 32-slot smem exchange, ONE syncwarp per batch.
// Phase 2: lane=(ff, j=lane&7): LDS.64 fp16 table chunk -> 2 FMA -> stcs.
// ---------------------------------------------------------------------------
__global__ void __launch_bounds__(256, 8) dfe_eval(
    const float* __restrict__ x, float* __restrict__ out)
{
    __shared__ h4     stab[4 * TAB_S];
    __shared__ float  sthr[4 * THR_S];
    __shared__ float2 sxch[8][2][32];    // per-warp double-buffered exchange

    int tid = threadIdx.x;
    int quad = blockIdx.x;
    int bbase = blockIdx.y * ROWS_PER_BLOCK;

    #pragma unroll
    for (int ff = 0; ff < 4; ff++)
        for (int i = tid; i < 520; i += 256)
            stab[ff * TAB_S + i] = g_tab_h[(quad * 4 + ff) * 520 + i];
    for (int i = tid; i < 4 * 64; i += 256)
        sthr[(i >> 6) * THR_S + (i & 63)] = g_thr[quad * 256 + i];
    __syncthreads();

    int lane = tid & 31, w = tid >> 5;
    int rrow = lane & 7;       // phase-1 row within batch
    int ff   = lane >> 3;      // feature within quad (both phases)
    int j    = lane & 7;       // phase-2 e-pair

    const float* thrp = sthr + ff * THR_S;
    const h4*    tabf = stab + ff * TAB_S;

    int rb0 = bbase + w * (ROWS_PER_BLOCK / 8);
    const float* xpb  = x   + (size_t)rb0 * FN + quad * 4 + ff;
    float*       outb = out + (size_t)rb0 * (FN * EN) + quad * 64 + ff * 16 + j * 2;

    float xs = __ldg(xpb + (size_t)rrow * FN);
    int   seg = seg_search(thrp, xs);

    #pragma unroll 4
    for (int batch = 0; batch < BATCHES; batch++) {
        float2* xch = sxch[w][batch & 1];
        xch[lane] = make_float2(xs, __int_as_float(seg));
        __syncwarp();
        if (batch < BATCHES - 1)
            xs = __ldg(xpb + (size_t)((batch + 1) * 8 + rrow) * FN);

        float* orow = outb + (size_t)(batch * 8) * (FN * EN);
        #pragma unroll
        for (int r2 = 0; r2 < 8; r2++) {
            float2 e = xch[(lane & 24) | r2];   // slot of (rrow=r2, ff)
            int sg = __float_as_int(e.y);
            h4 v = tabf[sg * 8 + j];
            float2 a = __half22float2(v.a);
            float2 c = __half22float2(v.c);
            float2 o;
            o.x = fmaf(a.x, e.x, c.x);
            o.y = fmaf(a.y, e.x, c.y);
            __stcs((float2*)(orow + (size_t)r2 * (FN * EN)), o);
        }

        if (batch < BATCHES - 1) seg = seg_search(thrp, xs);
        // no trailing syncwarp: next batch writes the OTHER buffer; this one
        // is only rewritten 2 batches later, past the next syncwarp (which
        // every lane must reach before any lane can overwrite).
    }
}

extern "C" void kernel_launch(void* const* d_in, const int* in_sizes, int n_in,
                              void* d_out, int out_size)
{
    const float* x  = (const float*)d_in[0];
    const float* W1 = (const float*)d_in[1];
    const float* b1 = (const float*)d_in[2];
    const float* W2 = (const float*)d_in[3];
    const float* b2 = (const float*)d_in[4];
    float* out = (float*)d_out;

    dfe_precompute<<<FN, 128>>>(W1, b1, W2, b2);
    dfe_eval<<<dim3(FN / 4, BN / ROWS_PER_BLOCK), 256>>>(x, out);
}

// round 13
// speedup vs baseline: 1.2009x; 1.0477x over previous
#include <cuda_runtime.h>
#include <cuda_bf16.h>
#include <cuda_fp16.h>

// emb[b,f,e] = b2[f,e] + sum_h W2[f,e,h]*relu(x[b,f]*W1[f,h]+b1[f,h])
// Piecewise-linear-in-x: per f, 65 segments; emb = A(seg)*x + C(seg).
// fp16 segment row (64B): 8 x {half2 A, half2 C}.
// R13 = R5 inner loop; block = 2 features x 1024 rows (grid 1024 -> occupancy
// restored AND table refill amortized to ~8.5MB).

#define BN 16384
#define FN 128
#define HN 64
#define EN 16
#define THR_S 72        // threshold stride
#define TAB_S 524       // smem table stride in h4 units
#define ROWS_PER_BLOCK 1024
#define BATCHES 8       // per warp: 128 rows = 8 batches of 16

struct __align__(8) h4 { __half2 a, c; };

__device__ h4    g_tab_h[FN * 520];   // per f: 65 segs * 8 h4
__device__ float g_thr[FN * 64];      // sorted hinge thresholds per f

// ---------------------------------------------------------------------------
// Kernel 1: per-feature precompute. One block per f, 128 threads. (proven)
// ---------------------------------------------------------------------------
__global__ void __launch_bounds__(128) dfe_precompute(
    const float* __restrict__ W1, const float* __restrict__ b1,
    const float* __restrict__ W2, const float* __restrict__ b2)
{
    int f = blockIdx.x;
    int tid = threadIdx.x;

    __shared__ float sw[HN], sb[HN], tv_[HN], st[HN];
    __shared__ int   sidx[HN];
    __shared__ float sv[EN * HN];
    __shared__ float stab[65 * 32];

    for (int i = tid; i < EN * HN; i += 128) sv[i] = W2[f * EN * HN + i];

    if (tid < HN) {
        float w = W1[f * HN + tid];
        float b = b1[f * HN + tid];
        sw[tid] = w; sb[tid] = b;
        tv_[tid] = (w != 0.0f) ? (-b / w) : 3.0e38f;  // sentinel: never crossed
    }
    __syncthreads();

    // stable rank-sort of 64 thresholds
    if (tid < HN) {
        float tv = tv_[tid];
        int r = 0;
        for (int j = 0; j < HN; j++) {
            float tj = tv_[j];
            r += (tj < tv) || (tj == tv && j < tid);
        }
        st[r] = tv;
        sidx[r] = tid;
    }
    __syncthreads();

    if (tid < HN) g_thr[f * HN + tid] = st[tid];

    // segment walk: 16 threads, one per e (all operands in smem)
    if (tid < EN) {
        int e = tid;
        const float* w2 = sv + e * HN;
        float A = 0.0f;
        float C = b2[f * EN + e];
        for (int h = 0; h < HN; h++) {
            float w = sw[h], b = sb[h], v = w2[h];
            float m = (w < 0.0f) ? 1.0f : 0.0f;            // active at x=-inf
            A += m * w * v;
            C += m * b * v;
            C += (w == 0.0f) ? fmaxf(b, 0.0f) * v : 0.0f;  // constant hinge
        }
        int grp = e >> 1, par = e & 1;
        for (int s = 0; s <= 64; s++) {
            stab[s * 32 + grp * 4 + par]     = A;
            stab[s * 32 + grp * 4 + 2 + par] = C;
            if (s < 64) {
                int h = sidx[s];
                float w = sw[h], b = sb[h], v = w2[h];
                float sg = (w > 0.0f) ? 1.0f : ((w < 0.0f) ? -1.0f : 0.0f);
                A += sg * w * v;
                C += sg * b * v;
            }
        }
    }
    __syncthreads();

    // pack fp32 staging -> fp16 table, coalesced writeback
    for (int i = tid; i < 520; i += 128) {
        int s = i >> 3, j = i & 7;
        const float* p = stab + s * 32 + j * 4;
        h4 v;
        v.a = __floats2half2_rn(p[0], p[1]);
        v.c = __floats2half2_rn(p[2], p[3]);
        g_tab_h[f * 520 + i] = v;
    }
}

// ---------------------------------------------------------------------------
// Branch-free count of { thr[t] <= xs } over 64 sorted entries (7 LDS).
// ---------------------------------------------------------------------------
__device__ __forceinline__ int seg_search(const float* __restrict__ thrp, float xs)
{
    int p = (thrp[31] <= xs) ? 32 : 0;
    p += (thrp[p + 15] <= xs) ? 16 : 0;
    p += (thrp[p + 7]  <= xs) ? 8  : 0;
    p += (thrp[p + 3]  <= xs) ? 4  : 0;
    p += (thrp[p + 1]  <= xs) ? 2  : 0;
    p += (thrp[p]      <= xs) ? 1  : 0;
    return p + ((thrp[p] <= xs) ? 1 : 0);   // in [0,64]
}

// ---------------------------------------------------------------------------
// Kernel 2: evaluation. Block = 2 features ("pair") x 1024 rows, 256 threads.
// grid (64,16)=1024 blocks (~7/SM). Warp owns 128 rows as 8 batches of 16.
// Phase 1: lane=(ff=lane>>4, rrow=lane&15): 32 distinct searches; results via
//   double-buffered 32-slot smem exchange, ONE syncwarp per batch.
// Phase 2: lane=(r01=lane>>4, ff2=(lane>>3)&1, j=lane&7): 8 passes x 2 rows;
//   broadcast exchange LDS, table LDS.64, 2 FMA, STG.64 (2 rows x 128B each).
// ---------------------------------------------------------------------------
__global__ void __launch_bounds__(256, 8) dfe_eval(
    const float* __restrict__ x, float* __restrict__ out)
{
    __shared__ h4     stab[2 * TAB_S];
    __shared__ float  sthr[2 * THR_S];
    __shared__ float2 sxch[8][2][32];    // per-warp double-buffered exchange

    int tid = threadIdx.x;
    int pairq = blockIdx.x;              // feature pair index: f = pairq*2 + ff
    int bbase = blockIdx.y * ROWS_PER_BLOCK;

    #pragma unroll
    for (int ff = 0; ff < 2; ff++)
        for (int i = tid; i < 520; i += 256)
            stab[ff * TAB_S + i] = g_tab_h[(pairq * 2 + ff) * 520 + i];
    for (int i = tid; i < 2 * 64; i += 256)
        sthr[(i >> 6) * THR_S + (i & 63)] = g_thr[pairq * 128 + i];
    __syncthreads();

    int lane = tid & 31, w = tid >> 5;
    int rrow = lane & 15;           // phase-1 row within 16-row batch
    int ff   = lane >> 4;           // phase-1 feature (0-1)
    int r01  = lane >> 4;           // phase-2 row parity (0-1)
    int ff2  = (lane >> 3) & 1;     // phase-2 feature
    int j    = lane & 7;            // phase-2 e-pair

    const float* thrp = sthr + ff * THR_S;
    const h4*    tabf = stab + ff2 * TAB_S;

    int rb0 = bbase + w * 128;
    const float* xpb  = x   + (size_t)rb0 * FN + pairq * 2 + ff;
    float*       outb = out + (size_t)rb0 * (FN * EN) + pairq * 32 + ff2 * 16 + j * 2;

    float xs = __ldg(xpb + (size_t)rrow * FN);
    int   seg = seg_search(thrp, xs);

    #pragma unroll
    for (int batch = 0; batch < BATCHES; batch++) {
        float2* xch = sxch[w][batch & 1];
        xch[lane] = make_float2(xs, __int_as_float(seg));
        __syncwarp();
        if (batch < BATCHES - 1)
            xs = __ldg(xpb + (size_t)((batch + 1) * 16 + rrow) * FN);

        float* orow = outb + (size_t)(batch * 16) * (FN * EN);
        #pragma unroll
        for (int p = 0; p < 8; p++) {
            int row = p * 2 + r01;
            float2 e = xch[ff2 * 16 + row];   // broadcast across 8 j lanes
            int sg = __float_as_int(e.y);
            h4 v = tabf[sg * 8 + j];
            float2 a = __half22float2(v.a);
            float2 c = __half22float2(v.c);
            float2 o;
            o.x = fmaf(a.x, e.x, c.x);
            o.y = fmaf(a.y, e.x, c.y);
            __stcs((float2*)(orow + (size_t)row * (FN * EN)), o);
        }

        if (batch < BATCHES - 1) seg = seg_search(thrp, xs);
        // no trailing syncwarp: next batch writes the OTHER buffer; this one
        // is rewritten 2 batches later, past the next syncwarp.
    }
}

extern "C" void kernel_launch(void* const* d_in, const int* in_sizes, int n_in,
                              void* d_out, int out_size)
{
    const float* x  = (const float*)d_in[0];
    const float* W1 = (const float*)d_in[1];
    const float* b1 = (const float*)d_in[2];
    const float* W2 = (const float*)d_in[3];
    const float* b2 = (const float*)d_in[4];
    float* out = (float*)d_out;

    dfe_precompute<<<FN, 128>>>(W1, b1, W2, b2);
    dfe_eval<<<dim3(FN / 2, BN / ROWS_PER_BLOCK), 256>>>(x, out);
}

// round 14
// speedup vs baseline: 1.2839x; 1.0692x over previous
#include <cuda_runtime.h>
#include <cuda_bf16.h>
#include <cuda_fp16.h>

// emb[b,f,e] = b2[f,e] + sum_h W2[f,e,h]*relu(x[b,f]*W1[f,h]+b1[f,h])
// Piecewise-linear-in-x: per f, 65 segments; emb = A(seg)*x + C(seg).
// fp16 segment row (64B): 8 x {half2 A, half2 C}.
// R14 = R13 eval (unchanged, best: 30.75us) + prefix-scan-parallel precompute.

#define BN 16384
#define FN 128
#define HN 64
#define EN 16
#define THR_S 72        // threshold stride
#define TAB_S 524       // smem table stride in h4 units
#define ROWS_PER_BLOCK 1024
#define BATCHES 8       // per warp: 128 rows = 8 batches of 16

struct __align__(8) h4 { __half2 a, c; };

__device__ h4    g_tab_h[FN * 520];   // per f: 65 segs * 8 h4
__device__ float g_thr[FN * 64];      // sorted hinge thresholds per f

// ---------------------------------------------------------------------------
// Kernel 1: per-feature precompute. One block per f, 128 threads.
// Segment walk parallelized as a prefix sum: thread = (e, g) with g in [0,8);
// each computes 8 local deltas, 8-lane shfl scan gives the prefix, xor-reduce
// gives the x=-inf base. Serial depth 65 -> ~11.
// ---------------------------------------------------------------------------
__global__ void __launch_bounds__(128) dfe_precompute(
    const float* __restrict__ W1, const float* __restrict__ b1,
    const float* __restrict__ W2, const float* __restrict__ b2)
{
    int f = blockIdx.x;
    int tid = threadIdx.x;

    __shared__ float sw[HN], sb[HN], tv_[HN], st[HN];
    __shared__ int   sidx[HN];
    __shared__ float sv[EN * HN];
    __shared__ float stab[65 * 32];

    // stage W2 row (4KB) with float4 loads
    {
        const float4* src = (const float4*)(W2 + (size_t)f * EN * HN);
        float4* dst = (float4*)sv;
        #pragma unroll
        for (int r = 0; r < 2; r++) dst[r * 128 + tid] = src[r * 128 + tid];
    }

    if (tid < HN) {
        float w = W1[f * HN + tid];
        float b = b1[f * HN + tid];
        sw[tid] = w; sb[tid] = b;
        tv_[tid] = (w != 0.0f) ? (-b / w) : 3.0e38f;  // sentinel: never crossed
    }
    __syncthreads();

    // stable rank-sort of 64 thresholds
    if (tid < HN) {
        float tv = tv_[tid];
        int r = 0;
        for (int j = 0; j < HN; j++) {
            float tj = tv_[j];
            r += (tj < tv) || (tj == tv && j < tid);
        }
        st[r] = tv;
        sidx[r] = tid;
    }
    __syncthreads();

    if (tid < HN) g_thr[f * HN + tid] = st[tid];

    // ---- parallel segment walk ----
    {
        int e = tid >> 3;          // embedding output 0..15
        int g = tid & 7;           // 8-lane subgroup position
        const float* w2 = sv + e * HN;

        // base (x=-inf active set) partial over h in [g*8, g*8+8)
        float bA = 0.0f, bC = 0.0f;
        #pragma unroll
        for (int k = 0; k < 8; k++) {
            int h = g * 8 + k;
            float w = sw[h], b = sb[h], v = w2[h];
            float m = (w < 0.0f) ? 1.0f : 0.0f;
            bA += m * w * v;
            bC += m * b * v;
            bC += (w == 0.0f) ? fmaxf(b, 0.0f) * v : 0.0f;
        }
        // xor-reduce across the 8-lane subgroup (all lanes get the total)
        #pragma unroll
        for (int d = 1; d < 8; d <<= 1) {
            bA += __shfl_xor_sync(0xffffffffu, bA, d, 8);
            bC += __shfl_xor_sync(0xffffffffu, bC, d, 8);
        }
        float A0 = bA;
        float C0 = bC + b2[f * EN + e];

        // local deltas for s in [g*8, g*8+8): inclusive local prefixes
        float preA[8], preC[8];
        float rA = 0.0f, rC = 0.0f;
        #pragma unroll
        for (int k = 0; k < 8; k++) {
            int s = g * 8 + k;
            int h = sidx[s];
            float w = sw[h], b = sb[h], v = w2[h];
            float sg = (w > 0.0f) ? 1.0f : ((w < 0.0f) ? -1.0f : 0.0f);
            rA += sg * w * v;
            rC += sg * b * v;
            preA[k] = rA; preC[k] = rC;
        }

        // inclusive scan of run totals across the 8-lane subgroup
        float sA = rA, sC = rC;
        #pragma unroll
        for (int d = 1; d < 8; d <<= 1) {
            float tA = __shfl_up_sync(0xffffffffu, sA, d, 8);
            float tC = __shfl_up_sync(0xffffffffu, sC, d, 8);
            if (g >= d) { sA += tA; sC += tC; }
        }
        float exA = sA - rA, exC = sC - rC;   // exclusive prefix of this lane

        // write stab: A(s) = A0 + (sum of deltas t < s)
        int grp = e >> 1, par = e & 1;
        #pragma unroll
        for (int k = 0; k < 8; k++) {
            int s = g * 8 + k;
            float A = A0 + exA + (k ? preA[k - 1] : 0.0f);
            float C = C0 + exC + (k ? preC[k - 1] : 0.0f);
            stab[s * 32 + grp * 4 + par]     = A;
            stab[s * 32 + grp * 4 + 2 + par] = C;
        }
        if (g == 7) {   // s = 64: after all 64 deltas
            stab[64 * 32 + grp * 4 + par]     = A0 + exA + preA[7];
            stab[64 * 32 + grp * 4 + 2 + par] = C0 + exC + preC[7];
        }
    }
    __syncthreads();

    // pack fp32 staging -> fp16 table, coalesced writeback
    for (int i = tid; i < 520; i += 128) {
        int s = i >> 3, j = i & 7;
        const float* p = stab + s * 32 + j * 4;
        h4 v;
        v.a = __floats2half2_rn(p[0], p[1]);
        v.c = __floats2half2_rn(p[2], p[3]);
        g_tab_h[f * 520 + i] = v;
    }
}

// ---------------------------------------------------------------------------
// Branch-free count of { thr[t] <= xs } over 64 sorted entries (7 LDS).
// ---------------------------------------------------------------------------
__device__ __forceinline__ int seg_search(const float* __restrict__ thrp, float xs)
{
    int p = (thrp[31] <= xs) ? 32 : 0;
    p += (thrp[p + 15] <= xs) ? 16 : 0;
    p += (thrp[p + 7]  <= xs) ? 8  : 0;
    p += (thrp[p + 3]  <= xs) ? 4  : 0;
    p += (thrp[p + 1]  <= xs) ? 2  : 0;
    p += (thrp[p]      <= xs) ? 1  : 0;
    return p + ((thrp[p] <= xs) ? 1 : 0);   // in [0,64]
}

// ---------------------------------------------------------------------------
// Kernel 2: evaluation — R13 EXACT (best measured: 30.75us).
// Block = 2 features x 1024 rows, 256 threads; grid (64,16)=1024 blocks.
// ---------------------------------------------------------------------------
__global__ void __launch_bounds__(256, 8) dfe_eval(
    const float* __restrict__ x, float* __restrict__ out)
{
    __shared__ h4     stab[2 * TAB_S];
    __shared__ float  sthr[2 * THR_S];
    __shared__ float2 sxch[8][2][32];    // per-warp double-buffered exchange

    int tid = threadIdx.x;
    int pairq = blockIdx.x;              // feature pair index: f = pairq*2 + ff
    int bbase = blockIdx.y * ROWS_PER_BLOCK;

    #pragma unroll
    for (int ff = 0; ff < 2; ff++)
        for (int i = tid; i < 520; i += 256)
            stab[ff * TAB_S + i] = g_tab_h[(pairq * 2 + ff) * 520 + i];
    for (int i = tid; i < 2 * 64; i += 256)
        sthr[(i >> 6) * THR_S + (i & 63)] = g_thr[pairq * 128 + i];
    __syncthreads();

    int lane = tid & 31, w = tid >> 5;
    int rrow = lane & 15;           // phase-1 row within 16-row batch
    int ff   = lane >> 4;           // phase-1 feature (0-1)
    int r01  = lane >> 4;           // phase-2 row parity (0-1)
    int ff2  = (lane >> 3) & 1;     // phase-2 feature
    int j    = lane & 7;            // phase-2 e-pair

    const float* thrp = sthr + ff * THR_S;
    const h4*    tabf = stab + ff2 * TAB_S;

    int rb0 = bbase + w * 128;
    const float* xpb  = x   + (size_t)rb0 * FN + pairq * 2 + ff;
    float*       outb = out + (size_t)rb0 * (FN * EN) + pairq * 32 + ff2 * 16 + j * 2;

    float xs = __ldg(xpb + (size_t)rrow * FN);
    int   seg = seg_search(thrp, xs);

    #pragma unroll
    for (int batch = 0; batch < BATCHES; batch++) {
        float2* xch = sxch[w][batch & 1];
        xch[lane] = make_float2(xs, __int_as_float(seg));
        __syncwarp();
        if (batch < BATCHES - 1)
            xs = __ldg(xpb + (size_t)((batch + 1) * 16 + rrow) * FN);

        float* orow = outb + (size_t)(batch * 16) * (FN * EN);
        #pragma unroll
        for (int p = 0; p < 8; p++) {
            int row = p * 2 + r01;
            float2 e = xch[ff2 * 16 + row];   // broadcast across 8 j lanes
            int sg = __float_as_int(e.y);
            h4 v = tabf[sg * 8 + j];
            float2 a = __half22float2(v.a);
            float2 c = __half22float2(v.c);
            float2 o;
            o.x = fmaf(a.x, e.x, c.x);
            o.y = fmaf(a.y, e.x, c.y);
            __stcs((float2*)(orow + (size_t)row * (FN * EN)), o);
        }

        if (batch < BATCHES - 1) seg = seg_search(thrp, xs);
        // no trailing syncwarp: next batch writes the OTHER buffer; this one
        // is rewritten 2 batches later, past the next syncwarp.
    }
}

extern "C" void kernel_launch(void* const* d_in, const int* in_sizes, int n_in,
                              void* d_out, int out_size)
{
    const float* x  = (const float*)d_in[0];
    const float* W1 = (const float*)d_in[1];
    const float* b1 = (const float*)d_in[2];
    const float* W2 = (const float*)d_in[3];
    const float* b2 = (const float*)d_in[4];
    float* out = (float*)d_out;

    dfe_precompute<<<FN, 128>>>(W1, b1, W2, b2);
    dfe_eval<<<dim3(FN / 2, BN / ROWS_PER_BLOCK), 256>>>(x, out);
}

// round 15
// speedup vs baseline: 1.3138x; 1.0233x over previous
#include <cuda_runtime.h>
#include <cuda_bf16.h>
#include <cuda_fp16.h>

// emb[b,f,e] = b2[f,e] + sum_h W2[f,e,h]*relu(x[b,f]*W1[f,h]+b1[f,h])
// Piecewise-linear-in-x: per f, 65 segments; emb = A(seg)*x + C(seg).
// fp16 segment row (64B): 8 x {half2 A, half2 C}.
// R15 = R14 exactly, with ROWS_PER_BLOCK 1024 -> 512 (grid 2048: fill occupancy).

#define BN 16384
#define FN 128
#define HN 64
#define EN 16
#define THR_S 72        // threshold stride
#define TAB_S 524       // smem table stride in h4 units
#define ROWS_PER_BLOCK 512
#define BATCHES 4       // per warp: 64 rows = 4 batches of 16

struct __align__(8) h4 { __half2 a, c; };

__device__ h4    g_tab_h[FN * 520];   // per f: 65 segs * 8 h4
__device__ float g_thr[FN * 64];      // sorted hinge thresholds per f

// ---------------------------------------------------------------------------
// Kernel 1: per-feature precompute. One block per f, 128 threads. (R14 exact)
// Prefix-scan-parallel segment walk: serial depth 65 -> ~11.
// ---------------------------------------------------------------------------
__global__ void __launch_bounds__(128) dfe_precompute(
    const float* __restrict__ W1, const float* __restrict__ b1,
    const float* __restrict__ W2, const float* __restrict__ b2)
{
    int f = blockIdx.x;
    int tid = threadIdx.x;

    __shared__ float sw[HN], sb[HN], tv_[HN], st[HN];
    __shared__ int   sidx[HN];
    __shared__ float sv[EN * HN];
    __shared__ float stab[65 * 32];

    // stage W2 row (4KB) with float4 loads
    {
        const float4* src = (const float4*)(W2 + (size_t)f * EN * HN);
        float4* dst = (float4*)sv;
        #pragma unroll
        for (int r = 0; r < 2; r++) dst[r * 128 + tid] = src[r * 128 + tid];
    }

    if (tid < HN) {
        float w = W1[f * HN + tid];
        float b = b1[f * HN + tid];
        sw[tid] = w; sb[tid] = b;
        tv_[tid] = (w != 0.0f) ? (-b / w) : 3.0e38f;  // sentinel: never crossed
    }
    __syncthreads();

    // stable rank-sort of 64 thresholds
    if (tid < HN) {
        float tv = tv_[tid];
        int r = 0;
        for (int j = 0; j < HN; j++) {
            float tj = tv_[j];
            r += (tj < tv) || (tj == tv && j < tid);
        }
        st[r] = tv;
        sidx[r] = tid;
    }
    __syncthreads();

    if (tid < HN) g_thr[f * HN + tid] = st[tid];

    // ---- parallel segment walk: thread = (e, g), g in [0,8) ----
    {
        int e = tid >> 3;
        int g = tid & 7;
        const float* w2 = sv + e * HN;

        // base (x=-inf active set) partial over h in [g*8, g*8+8)
        float bA = 0.0f, bC = 0.0f;
        #pragma unroll
        for (int k = 0; k < 8; k++) {
            int h = g * 8 + k;
            float w = sw[h], b = sb[h], v = w2[h];
            float m = (w < 0.0f) ? 1.0f : 0.0f;
            bA += m * w * v;
            bC += m * b * v;
            bC += (w == 0.0f) ? fmaxf(b, 0.0f) * v : 0.0f;
        }
        #pragma unroll
        for (int d = 1; d < 8; d <<= 1) {
            bA += __shfl_xor_sync(0xffffffffu, bA, d, 8);
            bC += __shfl_xor_sync(0xffffffffu, bC, d, 8);
        }
        float A0 = bA;
        float C0 = bC + b2[f * EN + e];

        // local deltas for s in [g*8, g*8+8): inclusive local prefixes
        float preA[8], preC[8];
        float rA = 0.0f, rC = 0.0f;
        #pragma unroll
        for (int k = 0; k < 8; k++) {
            int s = g * 8 + k;
            int h = sidx[s];
            float w = sw[h], b = sb[h], v = w2[h];
            float sg = (w > 0.0f) ? 1.0f : ((w < 0.0f) ? -1.0f : 0.0f);
            rA += sg * w * v;
            rC += sg * b * v;
            preA[k] = rA; preC[k] = rC;
        }

        // inclusive scan of run totals across the 8-lane subgroup
        float sA = rA, sC = rC;
        #pragma unroll
        for (int d = 1; d < 8; d <<= 1) {
            float tA = __shfl_up_sync(0xffffffffu, sA, d, 8);
            float tC = __shfl_up_sync(0xffffffffu, sC, d, 8);
            if (g >= d) { sA += tA; sC += tC; }
        }
        float exA = sA - rA, exC = sC - rC;

        int grp = e >> 1, par = e & 1;
        #pragma unroll
        for (int k = 0; k < 8; k++) {
            int s = g * 8 + k;
            float A = A0 + exA + (k ? preA[k - 1] : 0.0f);
            float C = C0 + exC + (k ? preC[k - 1] : 0.0f);
            stab[s * 32 + grp * 4 + par]     = A;
            stab[s * 32 + grp * 4 + 2 + par] = C;
        }
        if (g == 7) {
            stab[64 * 32 + grp * 4 + par]     = A0 + exA + preA[7];
            stab[64 * 32 + grp * 4 + 2 + par] = C0 + exC + preC[7];
        }
    }
    __syncthreads();

    // pack fp32 staging -> fp16 table, coalesced writeback
    for (int i = tid; i < 520; i += 128) {
        int s = i >> 3, j = i & 7;
        const float* p = stab + s * 32 + j * 4;
        h4 v;
        v.a = __floats2half2_rn(p[0], p[1]);
        v.c = __floats2half2_rn(p[2], p[3]);
        g_tab_h[f * 520 + i] = v;
    }
}

// ---------------------------------------------------------------------------
// Branch-free count of { thr[t] <= xs } over 64 sorted entries (7 LDS).
// ---------------------------------------------------------------------------
__device__ __forceinline__ int seg_search(const float* __restrict__ thrp, float xs)
{
    int p = (thrp[31] <= xs) ? 32 : 0;
    p += (thrp[p + 15] <= xs) ? 16 : 0;
    p += (thrp[p + 7]  <= xs) ? 8  : 0;
    p += (thrp[p + 3]  <= xs) ? 4  : 0;
    p += (thrp[p + 1]  <= xs) ? 2  : 0;
    p += (thrp[p]      <= xs) ? 1  : 0;
    return p + ((thrp[p] <= xs) ? 1 : 0);   // in [0,64]
}

// ---------------------------------------------------------------------------
// Kernel 2: evaluation — R13 inner loop; block = 2 features x 512 rows,
// 256 threads; grid (64,32)=2048 blocks (~2 waves of 8/SM -> occupancy up).
// ---------------------------------------------------------------------------
__global__ void __launch_bounds__(256, 8) dfe_eval(
    const float* __restrict__ x, float* __restrict__ out)
{
    __shared__ h4     stab[2 * TAB_S];
    __shared__ float  sthr[2 * THR_S];
    __shared__ float2 sxch[8][2][32];    // per-warp double-buffered exchange

    int tid = threadIdx.x;
    int pairq = blockIdx.x;              // feature pair index: f = pairq*2 + ff
    int bbase = blockIdx.y * ROWS_PER_BLOCK;

    #pragma unroll
    for (int ff = 0; ff < 2; ff++)
        for (int i = tid; i < 520; i += 256)
            stab[ff * TAB_S + i] = g_tab_h[(pairq * 2 + ff) * 520 + i];
    for (int i = tid; i < 2 * 64; i += 256)
        sthr[(i >> 6) * THR_S + (i & 63)] = g_thr[pairq * 128 + i];
    __syncthreads();

    int lane = tid & 31, w = tid >> 5;
    int rrow = lane & 15;           // phase-1 row within 16-row batch
    int ff   = lane >> 4;           // phase-1 feature (0-1)
    int r01  = lane >> 4;           // phase-2 row parity (0-1)
    int ff2  = (lane >> 3) & 1;     // phase-2 feature
    int j    = lane & 7;            // phase-2 e-pair

    const float* thrp = sthr + ff * THR_S;
    const h4*    tabf = stab + ff2 * TAB_S;

    int rb0 = bbase + w * (ROWS_PER_BLOCK / 8);
    const float* xpb  = x   + (size_t)rb0 * FN + pairq * 2 + ff;
    float*       outb = out + (size_t)rb0 * (FN * EN) + pairq * 32 + ff2 * 16 + j * 2;

    float xs = __ldg(xpb + (size_t)rrow * FN);
    int   seg = seg_search(thrp, xs);

    #pragma unroll
    for (int batch = 0; batch < BATCHES; batch++) {
        float2* xch = sxch[w][batch & 1];
        xch[lane] = make_float2(xs, __int_as_float(seg));
        __syncwarp();
        if (batch < BATCHES - 1)
            xs = __ldg(xpb + (size_t)((batch + 1) * 16 + rrow) * FN);

        float* orow = outb + (size_t)(batch * 16) * (FN * EN);
        #pragma unroll
        for (int p = 0; p < 8; p++) {
            int row = p * 2 + r01;
            float2 e = xch[ff2 * 16 + row];   // broadcast across 8 j lanes
            int sg = __float_as_int(e.y);
            h4 v = tabf[sg * 8 + j];
            float2 a = __half22float2(v.a);
            float2 c = __half22float2(v.c);
            float2 o;
            o.x = fmaf(a.x, e.x, c.x);
            o.y = fmaf(a.y, e.x, c.y);
            __stcs((float2*)(orow + (size_t)row * (FN * EN)), o);
        }

        if (batch < BATCHES - 1) seg = seg_search(thrp, xs);
        // no trailing syncwarp: next batch writes the OTHER buffer; this one
        // is rewritten 2 batches later, past the next syncwarp.
    }
}

extern "C" void kernel_launch(void* const* d_in, const int* in_sizes, int n_in,
                              void* d_out, int out_size)
{
    const float* x  = (const float*)d_in[0];
    const float* W1 = (const float*)d_in[1];
    const float* b1 = (const float*)d_in[2];
    const float* W2 = (const float*)d_in[3];
    const float* b2 = (const float*)d_in[4];
    float* out = (float*)d_out;

    dfe_precompute<<<FN, 128>>>(W1, b1, W2, b2);
    dfe_eval<<<dim3(FN / 2, BN / ROWS_PER_BLOCK), 256>>>(x, out);
}